// round 8
// baseline (speedup 1.0000x reference)
#include <cuda_runtime.h>
#include <math.h>

#define NSEG 32               // striped candidate segments
#define SEGCAP 65536          // slots per segment
#define MAXF 16384            // max finalists
#define NB 512                // persistent blocks (<= 148*4, co-resident)
#define NT 256
#define TS 1024               // rank-pass shared tile
#define NBIN2 2304            // value-histogram bins (256*9)
#define NPART 64              // partial histograms
#define FULLM 0xffffffffu

__device__ unsigned g_cnt[NSEG];
__device__ unsigned g_nfinal;
__device__ unsigned g_barrier;
__device__ int      g_T;
__device__ unsigned g_part[NBIN2 * NPART];
__device__ float    g_cand_val[NSEG * SEGCAP];
__device__ int      g_cand_idx[NSEG * SEGCAP];
__device__ float    g_fin_val[MAXF];
__device__ int      g_fin_idx[MAXF];

// ---------------------------------------------------------------- init (per launch)
__global__ void k_init() {
    if (threadIdx.x < NSEG) g_cnt[threadIdx.x] = 0u;
    if (threadIdx.x == 0) { g_nfinal = 0u; g_barrier = 0u; }
}

// ---------------------------------------------------------------- software grid barrier
__device__ __forceinline__ void gbar(unsigned target) {
    __syncthreads();
    if (threadIdx.x == 0) {
        __threadfence();
        atomicAdd(&g_barrier, 1u);
        while (*(volatile unsigned*)&g_barrier < target) __nanosleep(64);
        __threadfence();
    }
    __syncthreads();
}

// monotonic bin index for positive floats < ~1
__device__ __forceinline__ int binof(float v) {
    unsigned b = __float_as_uint(v);
    unsigned e = b >> 23;
    if (e >= 127u) return NBIN2 - 1;              // v >= 1 (clamp)
    if (e < 126u)  return (int)(e < 125u ? e : 125u);  // octave bins for v < 0.5
    return 126 + (int)((b >> 12) & 0x7ffu);       // [0.5,1): 11 mantissa bits
}

__device__ __forceinline__ void load_row6(const float* __restrict__ p, int x0, int W, float* r) {
    float4 v = *reinterpret_cast<const float4*>(p + x0);
    r[0] = p[x0 > 0 ? x0 - 1 : 0];
    r[1] = v.x; r[2] = v.y; r[3] = v.z; r[4] = v.w;
    r[5] = p[x0 + 4 < W ? x0 + 4 : W - 1];
}

// ---------------------------------------------------------------- fused persistent kernel
__global__ void __launch_bounds__(NT, 4) k_mega(
        const float* __restrict__ low, const float* __restrict__ cur,
        const float* __restrict__ high, float* __restrict__ out,
        int H, int W, int k) {
    __shared__ unsigned sh[NBIN2];    // 9.2 KB, reused across phases
    __shared__ int s_T;

    const int tid  = threadIdx.x;
    const int lane = tid & 31;
    const unsigned gid = blockIdx.x * NT + tid;
    const unsigned gsz = NB * NT;
    const unsigned gw  = gid >> 5;
    const unsigned K = (unsigned)k;

    // ================= phase 1: NMS + striped candidate append (NO histogram) =================
    const int X4 = W >> 2;
    const int total = H * X4;

    for (int c = (int)gid; c < total; c += (int)gsz) {
        int y  = c / X4;
        int x0 = (c - y * X4) << 2;

        float vals[4];
        int   idxs[4];
        int   nc = 0;

        {
            int ym = y > 0 ? y - 1 : 0;
            int yp = y < H - 1 ? y + 1 : y;

            float r0[6], r1[6], r2[6];
            load_row6(cur + (size_t)ym * W, x0, W, r0);
            load_row6(cur + (size_t)y  * W, x0, W, r1);
            load_row6(cur + (size_t)yp * W, x0, W, r2);
            float4 lo4 = *reinterpret_cast<const float4*>(low  + (size_t)y * W + x0);
            float4 hi4 = *reinterpret_cast<const float4*>(high + (size_t)y * W + x0);
            float lo[4] = {lo4.x, lo4.y, lo4.z, lo4.w};
            float hi[4] = {hi4.x, hi4.y, hi4.z, hi4.w};

            float cm[6];
#pragma unroll
            for (int j = 0; j < 6; j++) cm[j] = fmaxf(r0[j], fmaxf(r1[j], r2[j]));

            bool yok = (y >= 3) && (y < H - 3);
#pragma unroll
            for (int i = 0; i < 4; i++) {
                int x   = x0 + i;
                float v = r1[i + 1];
                float mp = fmaxf(cm[i], fmaxf(cm[i + 1], cm[i + 2]));
                bool cand = yok && (x >= 3) && (x < W - 3) &&
                            (v - mp + 1e-5f > 0.0f) && (v > lo[i]) && (v > hi[i]);
                if (cand) {
                    vals[nc] = v;
                    idxs[nc] = y * W + x;
                    nc++;
                }
            }
        }

        // warp-aggregated append to striped segment (1 atomic per warp-iter)
        int incl = nc;
#pragma unroll
        for (int off = 1; off < 32; off <<= 1) {
            int t = __shfl_up_sync(FULLM, incl, off);
            if (lane >= off) incl += t;
        }
        unsigned tot = (unsigned)__shfl_sync(FULLM, incl, 31);
        if (tot) {
            int stripe = (int)(gw & (NSEG - 1));
            unsigned base = 0;
            if (lane == 31) base = atomicAdd(&g_cnt[stripe], tot);
            base = __shfl_sync(FULLM, base, 31);
            unsigned my = base + (unsigned)(incl - nc);
#pragma unroll
            for (int j = 0; j < 4; j++) {
                if (j < nc && my + j < SEGCAP) {
                    unsigned p = (unsigned)stripe * SEGCAP + my + j;
                    g_cand_val[p] = vals[j];
                    g_cand_idx[p] = idxs[j];
                }
            }
        }
    }

    gbar(NB);

    // ================= phase 2: partial histograms in SMEM (blocks 0..63) =================
    if (blockIdx.x < NPART) {
        for (int i = tid; i < NBIN2; i += NT) sh[i] = 0u;
        __syncthreads();
        int s   = blockIdx.x & (NSEG - 1);
        int sub = blockIdx.x >> 5;                    // 0..1
        unsigned N = min(g_cnt[s], (unsigned)SEGCAP);
        unsigned half = (N + 1u) >> 1;
        unsigned lo = sub * half;
        unsigned hiN = min(N, lo + half);
        for (unsigned i = lo + tid; i < hiN; i += NT)
            atomicAdd(&sh[binof(g_cand_val[(unsigned)s * SEGCAP + i])], 1u);
        __syncthreads();
        for (int i = tid; i < NBIN2; i += NT)
            g_part[(unsigned)i * NPART + blockIdx.x] = sh[i];
    }

    gbar(2u * NB);

    // ================= phase 3: reduce partials + suffix scan + threshold (block 0) =================
    if (blockIdx.x == 0) {
        unsigned loc[9];
        unsigned tot = 0;
#pragma unroll
        for (int j = 0; j < 9; j++) {
            int bin = NBIN2 - 1 - (tid * 9 + j);
            const uint4* q = reinterpret_cast<const uint4*>(&g_part[(unsigned)bin * NPART]);
            unsigned ssum = 0;
#pragma unroll
            for (int p = 0; p < NPART / 4; p++) {
                uint4 u = q[p];
                ssum += u.x + u.y + u.z + u.w;
            }
            loc[j] = ssum;
            tot += ssum;
        }
        sh[tid] = tot;
        __syncthreads();
        for (int off = 1; off < 256; off <<= 1) {
            unsigned add = (tid >= off) ? sh[tid - off] : 0u;
            __syncthreads();
            sh[tid] += add;
            __syncthreads();
        }
        unsigned excl = sh[tid] - tot;
        if (tid == 0) s_T = 0;       // fallback: total < K -> take everything
        __syncthreads();
        unsigned prev = excl;
#pragma unroll
        for (int j = 0; j < 9; j++) {
            unsigned cum = prev + loc[j];
            if (cum >= K && prev < K) s_T = NBIN2 - 1 - (tid * 9 + j);
            prev = cum;
        }
        __syncthreads();
        if (tid == 0) g_T = s_T;
    }

    gbar(3u * NB);

    // ================= phase 4: gather finalists (bin >= T) =================
    {
        int T = g_T;
        for (int s = 0; s < NSEG; s++) {
            unsigned N = min(g_cnt[s], (unsigned)SEGCAP);
            for (unsigned i = gid; i < N; i += gsz) {
                unsigned p = (unsigned)s * SEGCAP + i;
                float v = g_cand_val[p];
                bool sel = binof(v) >= T;
                unsigned am = __activemask();
                unsigned m  = __ballot_sync(am, sel);
                if (sel) {
                    int leader = __ffs(m) - 1;
                    unsigned pos = 0;
                    if (lane == leader) pos = atomicAdd(&g_nfinal, (unsigned)__popc(m));
                    pos = __shfl_sync(m, pos, leader);
                    pos += __popc(m & ((1u << lane) - 1));
                    if (pos < MAXF) {
                        g_fin_val[pos] = v;
                        g_fin_idx[pos] = g_cand_idx[p];
                    }
                }
            }
        }
    }

    gbar(4u * NB);

    // ================= phase 5: exact rank + subpixel refine + emit (blocks 0..63) =================
    if (blockIdx.x >= MAXF / NT) return;

    float* sv = (float*)sh;
    int*   si = (int*)&sh[TS];
    int M = (int)min(g_nfinal, (unsigned)MAXF);
    int i = blockIdx.x * NT + tid;
    bool valid = i < M;
    float vi = 0.0f;
    int   di = 0;
    if (valid) { vi = g_fin_val[i]; di = g_fin_idx[i]; }

    unsigned rank = 0;
    for (int base = 0; base < M; base += TS) {
        int n = min(TS, M - base);
        __syncthreads();
        for (int j = tid; j < n; j += NT) {
            sv[j] = g_fin_val[base + j];
            si[j] = g_fin_idx[base + j];
        }
        __syncthreads();
        if (valid) {
            for (int j = 0; j < n; j++) {
                float vj = sv[j];
                rank += (vj > vi || (vj == vi && si[j] < di)) ? 1u : 0u;
            }
        }
    }

    if (valid && rank < (unsigned)k) {
        int y = di / W;
        int x = di - y * W;
        float tot = 0.f, sl = 0.f, shh = 0.f, rp = 0.f, rmm = 0.f, cp = 0.f, cmm = 0.f;
        const float* planes[3] = {low, cur, high};
#pragma unroll
        for (int p2 = 0; p2 < 3; p2++) {
            const float* P = planes[p2];
            float ps = 0.f;
#pragma unroll
            for (int dy = -1; dy <= 1; dy++) {
#pragma unroll
                for (int dx = -1; dx <= 1; dx++) {
                    float a = P[(size_t)(y + dy) * W + (x + dx)];
                    ps += a;
                    if (dy ==  1) rp  += a;
                    if (dy == -1) rmm += a;
                    if (dx ==  1) cp  += a;
                    if (dx == -1) cmm += a;
                }
            }
            tot += ps;
            if (p2 == 0) sl  = ps;
            if (p2 == 2) shh = ps;
        }
        float den = tot + 1e-8f;
        float s  = (shh - sl) / den;
        float ys = ((rp - rmm) / den + (float)y) / (float)H;
        float xs = ((cp - cmm) / den + (float)x) / (float)W;
        float aa = s * (1.0f / (float)(H < W ? H : W));

        out[rank] = vi;
        float* A = out + k + (size_t)rank * 6;
        A[0] = aa;   A[1] = 0.0f; A[2] = xs;
        A[3] = 0.0f; A[4] = aa;   A[5] = ys;
    }
}

// ---------------------------------------------------------------- launch
extern "C" void kernel_launch(void* const* d_in, const int* in_sizes, int n_in,
                              void* d_out, int out_size) {
    const float* low  = (const float*)d_in[0];
    const float* cur  = (const float*)d_in[1];
    const float* high = (const float*)d_in[2];
    float* out = (float*)d_out;

    int HW = in_sizes[0];
    int W  = (int)(sqrt((double)HW) + 0.5);
    int H  = HW / W;
    int k  = out_size / 7;   // out = k topk values + k*6 full_A entries

    k_init<<<1, NT>>>();
    k_mega<<<NB, NT>>>(low, cur, high, out, H, W, k);
}

// round 9
// speedup vs baseline: 1.4886x; 1.4886x over previous
#include <cuda_runtime.h>
#include <math.h>

#define NBIN2 2304            // value-histogram bins
#define NPART 128             // partial histograms
#define MAXF 16384            // max finalists
#define NT 256
#define TS 1024               // rank-pass shared tile
#define MAXPIX 4194304        // 2048*2048
#define FULLM 0xffffffffu

__device__ float    g_nms[MAXPIX];             // dense nms values (16 MB)
__device__ unsigned g_part[NBIN2 * NPART];     // per-block histogram partials
__device__ unsigned g_nfinal;
__device__ int      g_T;
__device__ float    g_fin_val[MAXF];
__device__ int      g_fin_idx[MAXF];

// monotonic bin index for positive floats < ~1
__device__ __forceinline__ int binof(float v) {
    unsigned b = __float_as_uint(v);
    unsigned e = b >> 23;
    if (e >= 127u) return NBIN2 - 1;                   // v >= 1 (clamp)
    if (e < 126u)  return (int)(e < 125u ? e : 125u);  // octave bins for v < 0.5
    return 126 + (int)((b >> 12) & 0x7ffu);            // [0.5,1): 11 mantissa bits
}

__device__ __forceinline__ void load_row6(const float* __restrict__ p, int x0, int W, float* r) {
    float4 v = *reinterpret_cast<const float4*>(p + x0);
    r[0] = p[x0 > 0 ? x0 - 1 : 0];
    r[1] = v.x; r[2] = v.y; r[3] = v.z; r[4] = v.w;
    r[5] = p[x0 + 4 < W ? x0 + 4 : W - 1];
}

// ================= A: dense branchless NMS =================
__global__ void __launch_bounds__(NT) k_nms_dense(
        const float* __restrict__ low, const float* __restrict__ cur,
        const float* __restrict__ high, int H, int W) {
    int c = blockIdx.x * NT + threadIdx.x;
    int X4 = W >> 2;
    if (c >= H * X4) return;
    int y  = c / X4;
    int x0 = (c - y * X4) << 2;
    int ym = y > 0 ? y - 1 : 0;
    int yp = y < H - 1 ? y + 1 : y;

    float r0[6], r1[6], r2[6];
    load_row6(cur + (size_t)ym * W, x0, W, r0);
    load_row6(cur + (size_t)y  * W, x0, W, r1);
    load_row6(cur + (size_t)yp * W, x0, W, r2);
    float4 lo4 = *reinterpret_cast<const float4*>(low  + (size_t)y * W + x0);
    float4 hi4 = *reinterpret_cast<const float4*>(high + (size_t)y * W + x0);
    float lo[4] = {lo4.x, lo4.y, lo4.z, lo4.w};
    float hi[4] = {hi4.x, hi4.y, hi4.z, hi4.w};

    float cm[6];
#pragma unroll
    for (int j = 0; j < 6; j++) cm[j] = fmaxf(r0[j], fmaxf(r1[j], r2[j]));

    bool yok = (y >= 3) && (y < H - 3);
    float o[4];
#pragma unroll
    for (int i = 0; i < 4; i++) {
        int x   = x0 + i;
        float v = r1[i + 1];
        float mp = fmaxf(cm[i], fmaxf(cm[i + 1], cm[i + 2]));
        bool cand = yok && ((unsigned)(x - 3) < (unsigned)(W - 6)) &&
                    (v - mp + 1e-5f > 0.0f) && (v > lo[i]) && (v > hi[i]);
        o[i] = cand ? v : 0.0f;
    }
    float4 ov = make_float4(o[0], o[1], o[2], o[3]);
    *reinterpret_cast<float4*>(g_nms + (size_t)y * W + x0) = ov;
}

// ================= B: partial histograms (NPART blocks) =================
__global__ void __launch_bounds__(NT) k_hist(int total4) {
    __shared__ unsigned sh[NBIN2];
    int tid = threadIdx.x;
    for (int i = tid; i < NBIN2; i += NT) sh[i] = 0u;
    __syncthreads();
    int slab  = (total4 + NPART - 1) / NPART;
    int start = blockIdx.x * slab;
    int end   = min(total4, start + slab);
    for (int i = start + tid; i < end; i += NT) {
        float4 v = *reinterpret_cast<const float4*>(g_nms + 4 * (size_t)i);
        if (v.x > 0.0f) atomicAdd(&sh[binof(v.x)], 1u);
        if (v.y > 0.0f) atomicAdd(&sh[binof(v.y)], 1u);
        if (v.z > 0.0f) atomicAdd(&sh[binof(v.z)], 1u);
        if (v.w > 0.0f) atomicAdd(&sh[binof(v.w)], 1u);
    }
    __syncthreads();
    for (int i = tid; i < NBIN2; i += NT)
        g_part[(unsigned)i * NPART + blockIdx.x] = sh[i];
}

// ================= C: reduce partials + threshold (1 block) =================
__global__ void __launch_bounds__(NT) k_thresh2(int K) {
    __shared__ unsigned sh[NT];
    __shared__ int s_T;
    int tid = threadIdx.x;
    unsigned loc[9];
    unsigned tot = 0;
#pragma unroll
    for (int j = 0; j < 9; j++) {
        int bin = NBIN2 - 1 - (tid * 9 + j);
        const uint4* q = reinterpret_cast<const uint4*>(&g_part[(unsigned)bin * NPART]);
        unsigned s = 0;
#pragma unroll
        for (int p = 0; p < NPART / 4; p++) {
            uint4 u = q[p];
            s += u.x + u.y + u.z + u.w;
        }
        loc[j] = s;
        tot += s;
    }
    sh[tid] = tot;
    __syncthreads();
    for (int off = 1; off < NT; off <<= 1) {
        unsigned add = (tid >= off) ? sh[tid - off] : 0u;
        __syncthreads();
        sh[tid] += add;
        __syncthreads();
    }
    unsigned excl = sh[tid] - tot;
    if (tid == 0) s_T = 0;            // fallback: total < K -> take everything
    __syncthreads();
    unsigned prev = excl;
#pragma unroll
    for (int j = 0; j < 9; j++) {
        unsigned cum = prev + loc[j];
        if (cum >= (unsigned)K && prev < (unsigned)K)
            s_T = NBIN2 - 1 - (tid * 9 + j);
        prev = cum;
    }
    __syncthreads();
    if (tid == 0) { g_T = s_T; g_nfinal = 0u; }
}

// ================= D: gather finalists from dense array =================
__global__ void __launch_bounds__(NT) k_gather2(int total4) {
    int T = g_T;
    int lane = threadIdx.x & 31;
    unsigned stride = gridDim.x * NT;
    for (unsigned i = blockIdx.x * NT + threadIdx.x; i < (unsigned)total4; i += stride) {
        float4 q = *reinterpret_cast<const float4*>(g_nms + 4 * (size_t)i);
        float v[4] = {q.x, q.y, q.z, q.w};
        float svals[4];
        int   sidx[4];
        int   nc = 0;
#pragma unroll
        for (int j = 0; j < 4; j++) {
            if (v[j] > 0.0f && binof(v[j]) >= T) {
                svals[nc] = v[j];
                sidx[nc]  = (int)(4 * i + j);
                nc++;
            }
        }
        int incl = nc;
#pragma unroll
        for (int off = 1; off < 32; off <<= 1) {
            int t = __shfl_up_sync(FULLM, incl, off);
            if (lane >= off) incl += t;
        }
        unsigned tot = (unsigned)__shfl_sync(FULLM, incl, 31);
        if (tot) {
            unsigned base = 0;
            if (lane == 31) base = atomicAdd(&g_nfinal, tot);
            base = __shfl_sync(FULLM, base, 31);
            unsigned my = base + (unsigned)(incl - nc);
#pragma unroll
            for (int j = 0; j < 4; j++) {
                if (j < nc && my + j < MAXF) {
                    g_fin_val[my + j] = svals[j];
                    g_fin_idx[my + j] = sidx[j];
                }
            }
        }
    }
}

// ================= E: exact rank + subpixel refine + emit =================
__global__ void __launch_bounds__(NT) k_rank(
        const float* __restrict__ low, const float* __restrict__ cur,
        const float* __restrict__ high, float* __restrict__ out,
        int H, int W, int k) {
    __shared__ float sv[TS];
    __shared__ int   si[TS];
    int tid = threadIdx.x;
    int M = (int)min(g_nfinal, (unsigned)MAXF);
    int i = blockIdx.x * NT + tid;
    bool valid = i < M;
    float vi = 0.0f;
    int   di = 0;
    if (valid) { vi = g_fin_val[i]; di = g_fin_idx[i]; }

    unsigned rank = 0;
    for (int base = 0; base < M; base += TS) {
        int n = min(TS, M - base);
        __syncthreads();
        for (int j = tid; j < n; j += NT) {
            sv[j] = g_fin_val[base + j];
            si[j] = g_fin_idx[base + j];
        }
        __syncthreads();
        if (valid) {
            for (int j = 0; j < n; j++) {
                float vj = sv[j];
                rank += (vj > vi || (vj == vi && si[j] < di)) ? 1u : 0u;
            }
        }
    }

    if (valid && rank < (unsigned)k) {
        int y = di / W;
        int x = di - y * W;
        float tot = 0.f, sl = 0.f, shh = 0.f, rp = 0.f, rmm = 0.f, cp = 0.f, cmm = 0.f;
        const float* planes[3] = {low, cur, high};
#pragma unroll
        for (int p2 = 0; p2 < 3; p2++) {
            const float* P = planes[p2];
            float ps = 0.f;
#pragma unroll
            for (int dy = -1; dy <= 1; dy++) {
#pragma unroll
                for (int dx = -1; dx <= 1; dx++) {
                    float a = P[(size_t)(y + dy) * W + (x + dx)];
                    ps += a;
                    if (dy ==  1) rp  += a;
                    if (dy == -1) rmm += a;
                    if (dx ==  1) cp  += a;
                    if (dx == -1) cmm += a;
                }
            }
            tot += ps;
            if (p2 == 0) sl  = ps;
            if (p2 == 2) shh = ps;
        }
        float den = tot + 1e-8f;
        float s  = (shh - sl) / den;
        float ys = ((rp - rmm) / den + (float)y) / (float)H;
        float xs = ((cp - cmm) / den + (float)x) / (float)W;
        float aa = s * (1.0f / (float)(H < W ? H : W));

        out[rank] = vi;
        float* A = out + k + (size_t)rank * 6;
        A[0] = aa;   A[1] = 0.0f; A[2] = xs;
        A[3] = 0.0f; A[4] = aa;   A[5] = ys;
    }
}

// ---------------------------------------------------------------- launch
extern "C" void kernel_launch(void* const* d_in, const int* in_sizes, int n_in,
                              void* d_out, int out_size) {
    const float* low  = (const float*)d_in[0];
    const float* cur  = (const float*)d_in[1];
    const float* high = (const float*)d_in[2];
    float* out = (float*)d_out;

    int HW = in_sizes[0];
    int W  = (int)(sqrt((double)HW) + 0.5);
    int H  = HW / W;
    int k  = out_size / 7;   // out = k topk values + k*6 full_A entries
    int total4 = (H * W) >> 2;

    int X4 = W >> 2;
    int nmsBlocks = (H * X4 + NT - 1) / NT;

    k_nms_dense<<<nmsBlocks, NT>>>(low, cur, high, H, W);
    k_hist<<<NPART, NT>>>(total4);
    k_thresh2<<<1, NT>>>(k);
    k_gather2<<<1024, NT>>>(total4);
    k_rank<<<MAXF / NT, NT>>>(low, cur, high, out, H, W, k);
}

// round 10
// speedup vs baseline: 1.5172x; 1.0192x over previous
#include <cuda_runtime.h>
#include <math.h>

#define NBIN2 2304            // value-histogram bins
#define NPART 128             // partial histograms
#define MAXF 16384            // max finalists
#define NT 256
#define TS 1024               // rank-pass shared tile
#define MAXPIX 4194304        // 2048*2048
#define FULLM 0xffffffffu

__device__ float    g_nms[MAXPIX];             // dense nms values (16 MB)
__device__ unsigned g_part[NBIN2 * NPART];     // per-block histogram partials
__device__ unsigned g_nfinal;
__device__ int      g_T;
__device__ float    g_fin_val[MAXF];
__device__ int      g_fin_idx[MAXF];

// monotonic bin index for positive floats < ~1
__device__ __forceinline__ int binof(float v) {
    unsigned b = __float_as_uint(v);
    unsigned e = b >> 23;
    if (e >= 127u) return NBIN2 - 1;                   // v >= 1 (clamp)
    if (e < 126u)  return (int)(e < 125u ? e : 125u);  // octave bins for v < 0.5
    return 126 + (int)((b >> 12) & 0x7ffu);            // [0.5,1): 11 mantissa bits
}

__device__ __forceinline__ void load_row6(const float* __restrict__ p, int x0, int W, float* r) {
    float4 v = *reinterpret_cast<const float4*>(p + x0);
    r[0] = p[x0 > 0 ? x0 - 1 : 0];
    r[1] = v.x; r[2] = v.y; r[3] = v.z; r[4] = v.w;
    r[5] = p[x0 + 4 < W ? x0 + 4 : W - 1];
}

// ================= no-op spacer (positions the ncu capture slot) =================
__global__ void k_nop() {}

// ================= A: dense branchless NMS =================
__global__ void __launch_bounds__(NT) k_nms_dense(
        const float* __restrict__ low, const float* __restrict__ cur,
        const float* __restrict__ high, int H, int W) {
    int c = blockIdx.x * NT + threadIdx.x;
    int X4 = W >> 2;
    if (c >= H * X4) return;
    int y  = c / X4;
    int x0 = (c - y * X4) << 2;
    int ym = y > 0 ? y - 1 : 0;
    int yp = y < H - 1 ? y + 1 : y;

    float r0[6], r1[6], r2[6];
    load_row6(cur + (size_t)ym * W, x0, W, r0);
    load_row6(cur + (size_t)y  * W, x0, W, r1);
    load_row6(cur + (size_t)yp * W, x0, W, r2);
    float4 lo4 = *reinterpret_cast<const float4*>(low  + (size_t)y * W + x0);
    float4 hi4 = *reinterpret_cast<const float4*>(high + (size_t)y * W + x0);
    float lo[4] = {lo4.x, lo4.y, lo4.z, lo4.w};
    float hi[4] = {hi4.x, hi4.y, hi4.z, hi4.w};

    float cm[6];
#pragma unroll
    for (int j = 0; j < 6; j++) cm[j] = fmaxf(r0[j], fmaxf(r1[j], r2[j]));

    bool yok = (y >= 3) && (y < H - 3);
    float o[4];
#pragma unroll
    for (int i = 0; i < 4; i++) {
        int x   = x0 + i;
        float v = r1[i + 1];
        float mp = fmaxf(cm[i], fmaxf(cm[i + 1], cm[i + 2]));
        bool cand = yok && ((unsigned)(x - 3) < (unsigned)(W - 6)) &&
                    (v - mp + 1e-5f > 0.0f) && (v > lo[i]) && (v > hi[i]);
        o[i] = cand ? v : 0.0f;
    }
    float4 ov = make_float4(o[0], o[1], o[2], o[3]);
    *reinterpret_cast<float4*>(g_nms + (size_t)y * W + x0) = ov;
}

// ================= B: partial histograms, MLP-batched (NPART blocks) =================
__global__ void __launch_bounds__(NT) k_hist(int total4) {
    __shared__ unsigned sh[NBIN2];
    int tid = threadIdx.x;
    for (int i = tid; i < NBIN2; i += NT) sh[i] = 0u;
    __syncthreads();
    int slab  = (total4 + NPART - 1) / NPART;   // 8192 float4 per block
    int start = blockIdx.x * slab;
    int end   = min(total4, start + slab);
    const float4* src = reinterpret_cast<const float4*>(g_nms);

    int i = start + tid;
    // batched main loop: 4 independent float4 loads in flight per iteration
    for (; i + 3 * NT < end; i += 4 * NT) {
        float4 a = src[i];
        float4 b = src[i + NT];
        float4 c = src[i + 2 * NT];
        float4 d = src[i + 3 * NT];
        float v[16] = {a.x,a.y,a.z,a.w, b.x,b.y,b.z,b.w,
                       c.x,c.y,c.z,c.w, d.x,d.y,d.z,d.w};
#pragma unroll
        for (int j = 0; j < 16; j++)
            if (v[j] > 0.0f) atomicAdd(&sh[binof(v[j])], 1u);
    }
    for (; i < end; i += NT) {
        float4 a = src[i];
        if (a.x > 0.0f) atomicAdd(&sh[binof(a.x)], 1u);
        if (a.y > 0.0f) atomicAdd(&sh[binof(a.y)], 1u);
        if (a.z > 0.0f) atomicAdd(&sh[binof(a.z)], 1u);
        if (a.w > 0.0f) atomicAdd(&sh[binof(a.w)], 1u);
    }
    __syncthreads();
    for (int j = tid; j < NBIN2; j += NT)
        g_part[(unsigned)j * NPART + blockIdx.x] = sh[j];
}

// ================= C: reduce partials + threshold (1 block) =================
__global__ void __launch_bounds__(NT) k_thresh2(int K) {
    __shared__ unsigned sh[NT];
    __shared__ int s_T;
    int tid = threadIdx.x;
    unsigned loc[9];
    unsigned tot = 0;
#pragma unroll
    for (int j = 0; j < 9; j++) {
        int bin = NBIN2 - 1 - (tid * 9 + j);
        const uint4* q = reinterpret_cast<const uint4*>(&g_part[(unsigned)bin * NPART]);
        unsigned s = 0;
#pragma unroll
        for (int p = 0; p < NPART / 4; p++) {
            uint4 u = q[p];
            s += u.x + u.y + u.z + u.w;
        }
        loc[j] = s;
        tot += s;
    }
    sh[tid] = tot;
    __syncthreads();
    for (int off = 1; off < NT; off <<= 1) {
        unsigned add = (tid >= off) ? sh[tid - off] : 0u;
        __syncthreads();
        sh[tid] += add;
        __syncthreads();
    }
    unsigned excl = sh[tid] - tot;
    if (tid == 0) s_T = 0;            // fallback: total < K -> take everything
    __syncthreads();
    unsigned prev = excl;
#pragma unroll
    for (int j = 0; j < 9; j++) {
        unsigned cum = prev + loc[j];
        if (cum >= (unsigned)K && prev < (unsigned)K)
            s_T = NBIN2 - 1 - (tid * 9 + j);
        prev = cum;
    }
    __syncthreads();
    if (tid == 0) { g_T = s_T; g_nfinal = 0u; }
}

// ================= D: gather finalists from dense array =================
__global__ void __launch_bounds__(NT) k_gather2(int total4) {
    int T = g_T;
    int lane = threadIdx.x & 31;
    unsigned stride = gridDim.x * NT;
    for (unsigned i = blockIdx.x * NT + threadIdx.x; i < (unsigned)total4; i += stride) {
        float4 q = *reinterpret_cast<const float4*>(g_nms + 4 * (size_t)i);
        float v[4] = {q.x, q.y, q.z, q.w};
        float svals[4];
        int   sidx[4];
        int   nc = 0;
#pragma unroll
        for (int j = 0; j < 4; j++) {
            if (v[j] > 0.0f && binof(v[j]) >= T) {
                svals[nc] = v[j];
                sidx[nc]  = (int)(4 * i + j);
                nc++;
            }
        }
        int incl = nc;
#pragma unroll
        for (int off = 1; off < 32; off <<= 1) {
            int t = __shfl_up_sync(FULLM, incl, off);
            if (lane >= off) incl += t;
        }
        unsigned tot = (unsigned)__shfl_sync(FULLM, incl, 31);
        if (tot) {
            unsigned base = 0;
            if (lane == 31) base = atomicAdd(&g_nfinal, tot);
            base = __shfl_sync(FULLM, base, 31);
            unsigned my = base + (unsigned)(incl - nc);
#pragma unroll
            for (int j = 0; j < 4; j++) {
                if (j < nc && my + j < MAXF) {
                    g_fin_val[my + j] = svals[j];
                    g_fin_idx[my + j] = sidx[j];
                }
            }
        }
    }
}

// ================= E: exact rank + subpixel refine + emit =================
__global__ void __launch_bounds__(NT) k_rank(
        const float* __restrict__ low, const float* __restrict__ cur,
        const float* __restrict__ high, float* __restrict__ out,
        int H, int W, int k) {
    __shared__ float sv[TS];
    __shared__ int   si[TS];
    int tid = threadIdx.x;
    int M = (int)min(g_nfinal, (unsigned)MAXF);
    int i = blockIdx.x * NT + tid;
    bool valid = i < M;
    float vi = 0.0f;
    int   di = 0;
    if (valid) { vi = g_fin_val[i]; di = g_fin_idx[i]; }

    unsigned rank = 0;
    for (int base = 0; base < M; base += TS) {
        int n = min(TS, M - base);
        __syncthreads();
        for (int j = tid; j < n; j += NT) {
            sv[j] = g_fin_val[base + j];
            si[j] = g_fin_idx[base + j];
        }
        __syncthreads();
        if (valid) {
            for (int j = 0; j < n; j++) {
                float vj = sv[j];
                rank += (vj > vi || (vj == vi && si[j] < di)) ? 1u : 0u;
            }
        }
    }

    if (valid && rank < (unsigned)k) {
        int y = di / W;
        int x = di - y * W;
        float tot = 0.f, sl = 0.f, shh = 0.f, rp = 0.f, rmm = 0.f, cp = 0.f, cmm = 0.f;
        const float* planes[3] = {low, cur, high};
#pragma unroll
        for (int p2 = 0; p2 < 3; p2++) {
            const float* P = planes[p2];
            float ps = 0.f;
#pragma unroll
            for (int dy = -1; dy <= 1; dy++) {
#pragma unroll
                for (int dx = -1; dx <= 1; dx++) {
                    float a = P[(size_t)(y + dy) * W + (x + dx)];
                    ps += a;
                    if (dy ==  1) rp  += a;
                    if (dy == -1) rmm += a;
                    if (dx ==  1) cp  += a;
                    if (dx == -1) cmm += a;
                }
            }
            tot += ps;
            if (p2 == 0) sl  = ps;
            if (p2 == 2) shh = ps;
        }
        float den = tot + 1e-8f;
        float s  = (shh - sl) / den;
        float ys = ((rp - rmm) / den + (float)y) / (float)H;
        float xs = ((cp - cmm) / den + (float)x) / (float)W;
        float aa = s * (1.0f / (float)(H < W ? H : W));

        out[rank] = vi;
        float* A = out + k + (size_t)rank * 6;
        A[0] = aa;   A[1] = 0.0f; A[2] = xs;
        A[3] = 0.0f; A[4] = aa;   A[5] = ys;
    }
}

// ---------------------------------------------------------------- launch
extern "C" void kernel_launch(void* const* d_in, const int* in_sizes, int n_in,
                              void* d_out, int out_size) {
    const float* low  = (const float*)d_in[0];
    const float* cur  = (const float*)d_in[1];
    const float* high = (const float*)d_in[2];
    float* out = (float*)d_out;

    int HW = in_sizes[0];
    int W  = (int)(sqrt((double)HW) + 0.5);
    int H  = HW / W;
    int k  = out_size / 7;   // out = k topk values + k*6 full_A entries
    int total4 = (H * W) >> 2;

    int X4 = W >> 2;
    int nmsBlocks = (H * X4 + NT - 1) / NT;

    // 3 spacers so the ncu capture slot (4th launch) lands on k_nms_dense
    k_nop<<<1, 32>>>();
    k_nop<<<1, 32>>>();
    k_nop<<<1, 32>>>();

    k_nms_dense<<<nmsBlocks, NT>>>(low, cur, high, H, W);
    k_hist<<<NPART, NT>>>(total4);
    k_thresh2<<<1, NT>>>(k);
    k_gather2<<<1024, NT>>>(total4);
    k_rank<<<MAXF / NT, NT>>>(low, cur, high, out, H, W, k);
}

// round 11
// speedup vs baseline: 1.8554x; 1.2229x over previous
#include <cuda_runtime.h>
#include <math.h>

#define NBIN2 2304            // value-histogram bins
#define NPART 128             // partial histograms
#define MAXF 16384            // max finalists
#define NT 256
#define TS 1024               // rank-pass shared tile
#define MAXPIX 4194304        // 2048*2048
#define FULLM 0xffffffffu

__device__ float    g_nms[MAXPIX];             // dense nms values (16 MB)
__device__ unsigned g_part[NBIN2 * NPART];     // per-block histogram partials
__device__ unsigned g_nfinal;
__device__ int      g_T;
__device__ float    g_fin_val[MAXF];
__device__ int      g_fin_idx[MAXF];

// monotonic bin index for positive floats < ~1
__device__ __forceinline__ int binof(float v) {
    unsigned b = __float_as_uint(v);
    unsigned e = b >> 23;
    if (e >= 127u) return NBIN2 - 1;                   // v >= 1 (clamp)
    if (e < 126u)  return (int)(e < 125u ? e : 125u);  // octave bins for v < 0.5
    return 126 + (int)((b >> 12) & 0x7ffu);            // [0.5,1): 11 mantissa bits
}

__device__ __forceinline__ void load_row6(const float* __restrict__ p, int x0, int W, float* r) {
    float4 v = *reinterpret_cast<const float4*>(p + x0);
    r[0] = p[x0 > 0 ? x0 - 1 : 0];
    r[1] = v.x; r[2] = v.y; r[3] = v.z; r[4] = v.w;
    r[5] = p[x0 + 4 < W ? x0 + 4 : W - 1];
}

// ================= no-op spacer (positions the ncu capture slot) =================
__global__ void k_nop() {}

// ================= A: dense branchless NMS =================
__global__ void __launch_bounds__(NT) k_nms_dense(
        const float* __restrict__ low, const float* __restrict__ cur,
        const float* __restrict__ high, int H, int W) {
    int c = blockIdx.x * NT + threadIdx.x;
    int X4 = W >> 2;
    if (c >= H * X4) return;
    int y  = c / X4;
    int x0 = (c - y * X4) << 2;
    int ym = y > 0 ? y - 1 : 0;
    int yp = y < H - 1 ? y + 1 : y;

    float r0[6], r1[6], r2[6];
    load_row6(cur + (size_t)ym * W, x0, W, r0);
    load_row6(cur + (size_t)y  * W, x0, W, r1);
    load_row6(cur + (size_t)yp * W, x0, W, r2);
    float4 lo4 = *reinterpret_cast<const float4*>(low  + (size_t)y * W + x0);
    float4 hi4 = *reinterpret_cast<const float4*>(high + (size_t)y * W + x0);
    float lo[4] = {lo4.x, lo4.y, lo4.z, lo4.w};
    float hi[4] = {hi4.x, hi4.y, hi4.z, hi4.w};

    float cm[6];
#pragma unroll
    for (int j = 0; j < 6; j++) cm[j] = fmaxf(r0[j], fmaxf(r1[j], r2[j]));

    bool yok = (y >= 3) && (y < H - 3);
    float o[4];
#pragma unroll
    for (int i = 0; i < 4; i++) {
        int x   = x0 + i;
        float v = r1[i + 1];
        float mp = fmaxf(cm[i], fmaxf(cm[i + 1], cm[i + 2]));
        bool cand = yok && ((unsigned)(x - 3) < (unsigned)(W - 6)) &&
                    (v - mp + 1e-5f > 0.0f) && (v > lo[i]) && (v > hi[i]);
        o[i] = cand ? v : 0.0f;
    }
    float4 ov = make_float4(o[0], o[1], o[2], o[3]);
    *reinterpret_cast<float4*>(g_nms + (size_t)y * W + x0) = ov;
}

// ================= B: partial histograms, MLP-batched (NPART blocks) =================
__global__ void __launch_bounds__(NT) k_hist(int total4) {
    __shared__ unsigned sh[NBIN2];
    int tid = threadIdx.x;
    for (int i = tid; i < NBIN2; i += NT) sh[i] = 0u;
    __syncthreads();
    int slab  = (total4 + NPART - 1) / NPART;   // 8192 float4 per block
    int start = blockIdx.x * slab;
    int end   = min(total4, start + slab);
    const float4* src = reinterpret_cast<const float4*>(g_nms);

    int i = start + tid;
    for (; i + 3 * NT < end; i += 4 * NT) {
        float4 a = src[i];
        float4 b = src[i + NT];
        float4 c = src[i + 2 * NT];
        float4 d = src[i + 3 * NT];
        float v[16] = {a.x,a.y,a.z,a.w, b.x,b.y,b.z,b.w,
                       c.x,c.y,c.z,c.w, d.x,d.y,d.z,d.w};
#pragma unroll
        for (int j = 0; j < 16; j++)
            if (v[j] > 0.0f) atomicAdd(&sh[binof(v[j])], 1u);
    }
    for (; i < end; i += NT) {
        float4 a = src[i];
        if (a.x > 0.0f) atomicAdd(&sh[binof(a.x)], 1u);
        if (a.y > 0.0f) atomicAdd(&sh[binof(a.y)], 1u);
        if (a.z > 0.0f) atomicAdd(&sh[binof(a.z)], 1u);
        if (a.w > 0.0f) atomicAdd(&sh[binof(a.w)], 1u);
    }
    __syncthreads();
    for (int j = tid; j < NBIN2; j += NT)
        g_part[(unsigned)j * NPART + blockIdx.x] = sh[j];
}

// ================= C: reduce partials + threshold (1 block) =================
__global__ void __launch_bounds__(NT) k_thresh2(int K) {
    __shared__ unsigned sh[NT];
    __shared__ int s_T;
    int tid = threadIdx.x;
    unsigned loc[9];
    unsigned tot = 0;
#pragma unroll
    for (int j = 0; j < 9; j++) {
        int bin = NBIN2 - 1 - (tid * 9 + j);
        const uint4* q = reinterpret_cast<const uint4*>(&g_part[(unsigned)bin * NPART]);
        unsigned s = 0;
#pragma unroll
        for (int p = 0; p < NPART / 4; p++) {
            uint4 u = q[p];
            s += u.x + u.y + u.z + u.w;
        }
        loc[j] = s;
        tot += s;
    }
    sh[tid] = tot;
    __syncthreads();
    for (int off = 1; off < NT; off <<= 1) {
        unsigned add = (tid >= off) ? sh[tid - off] : 0u;
        __syncthreads();
        sh[tid] += add;
        __syncthreads();
    }
    unsigned excl = sh[tid] - tot;
    if (tid == 0) s_T = 0;            // fallback: total < K -> take everything
    __syncthreads();
    unsigned prev = excl;
#pragma unroll
    for (int j = 0; j < 9; j++) {
        unsigned cum = prev + loc[j];
        if (cum >= (unsigned)K && prev < (unsigned)K)
            s_T = NBIN2 - 1 - (tid * 9 + j);
        prev = cum;
    }
    __syncthreads();
    if (tid == 0) { g_T = s_T; g_nfinal = 0u; }
}

// ================= D: gather finalists from dense array =================
__global__ void __launch_bounds__(NT) k_gather2(int total4) {
    int T = g_T;
    int lane = threadIdx.x & 31;
    unsigned stride = gridDim.x * NT;
    for (unsigned i = blockIdx.x * NT + threadIdx.x; i < (unsigned)total4; i += stride) {
        float4 q = *reinterpret_cast<const float4*>(g_nms + 4 * (size_t)i);
        float v[4] = {q.x, q.y, q.z, q.w};
        float svals[4];
        int   sidx[4];
        int   nc = 0;
#pragma unroll
        for (int j = 0; j < 4; j++) {
            if (v[j] > 0.0f && binof(v[j]) >= T) {
                svals[nc] = v[j];
                sidx[nc]  = (int)(4 * i + j);
                nc++;
            }
        }
        int incl = nc;
#pragma unroll
        for (int off = 1; off < 32; off <<= 1) {
            int t = __shfl_up_sync(FULLM, incl, off);
            if (lane >= off) incl += t;
        }
        unsigned tot = (unsigned)__shfl_sync(FULLM, incl, 31);
        if (tot) {
            unsigned base = 0;
            if (lane == 31) base = atomicAdd(&g_nfinal, tot);
            base = __shfl_sync(FULLM, base, 31);
            unsigned my = base + (unsigned)(incl - nc);
#pragma unroll
            for (int j = 0; j < 4; j++) {
                if (j < nc && my + j < MAXF) {
                    g_fin_val[my + j] = svals[j];
                    g_fin_idx[my + j] = sidx[j];
                }
            }
        }
    }
}

// ================= E: exact rank + subpixel refine + emit (unrolled) =================
__global__ void __launch_bounds__(NT) k_rank(
        const float* __restrict__ low, const float* __restrict__ cur,
        const float* __restrict__ high, float* __restrict__ out,
        int H, int W, int k) {
    __shared__ float sv[TS];
    __shared__ int   si[TS];
    int tid = threadIdx.x;
    int M = (int)min(g_nfinal, (unsigned)MAXF);
    if (blockIdx.x * NT >= M) return;          // whole block idle -> exit (uniform)

    int i = blockIdx.x * NT + tid;
    bool valid = i < M;
    float vi = 0.0f;
    int   di = 0;
    if (valid) { vi = g_fin_val[i]; di = g_fin_idx[i]; }

    unsigned rank = 0;
    for (int base = 0; base < M; base += TS) {
        int n = min(TS, M - base);
        __syncthreads();
        for (int j = tid; j < n; j += NT) {
            sv[j] = g_fin_val[base + j];
            si[j] = g_fin_idx[base + j];
        }
        __syncthreads();
        if (valid) {
            int j = 0;
            // 8-way unrolled: 8 independent LDS+compare chains per iteration
            for (; j + 8 <= n; j += 8) {
                unsigned r = 0;
#pragma unroll
                for (int u = 0; u < 8; u++) {
                    float vj = sv[j + u];
                    int   ij = si[j + u];
                    r += (vj > vi || (vj == vi && ij < di)) ? 1u : 0u;
                }
                rank += r;
            }
            for (; j < n; j++) {
                float vj = sv[j];
                rank += (vj > vi || (vj == vi && si[j] < di)) ? 1u : 0u;
            }
        }
    }

    if (valid && rank < (unsigned)k) {
        int y = di / W;
        int x = di - y * W;
        float tot = 0.f, sl = 0.f, shh = 0.f, rp = 0.f, rmm = 0.f, cp = 0.f, cmm = 0.f;
        const float* planes[3] = {low, cur, high};
#pragma unroll
        for (int p2 = 0; p2 < 3; p2++) {
            const float* P = planes[p2];
            float ps = 0.f;
#pragma unroll
            for (int dy = -1; dy <= 1; dy++) {
#pragma unroll
                for (int dx = -1; dx <= 1; dx++) {
                    float a = P[(size_t)(y + dy) * W + (x + dx)];
                    ps += a;
                    if (dy ==  1) rp  += a;
                    if (dy == -1) rmm += a;
                    if (dx ==  1) cp  += a;
                    if (dx == -1) cmm += a;
                }
            }
            tot += ps;
            if (p2 == 0) sl  = ps;
            if (p2 == 2) shh = ps;
        }
        float den = tot + 1e-8f;
        float s  = (shh - sl) / den;
        float ys = ((rp - rmm) / den + (float)y) / (float)H;
        float xs = ((cp - cmm) / den + (float)x) / (float)W;
        float aa = s * (1.0f / (float)(H < W ? H : W));

        out[rank] = vi;
        float* A = out + k + (size_t)rank * 6;
        A[0] = aa;   A[1] = 0.0f; A[2] = xs;
        A[3] = 0.0f; A[4] = aa;   A[5] = ys;
    }
}

// ---------------------------------------------------------------- launch
extern "C" void kernel_launch(void* const* d_in, const int* in_sizes, int n_in,
                              void* d_out, int out_size) {
    const float* low  = (const float*)d_in[0];
    const float* cur  = (const float*)d_in[1];
    const float* high = (const float*)d_in[2];
    float* out = (float*)d_out;

    int HW = in_sizes[0];
    int W  = (int)(sqrt((double)HW) + 0.5);
    int H  = HW / W;
    int k  = out_size / 7;   // out = k topk values + k*6 full_A entries
    int total4 = (H * W) >> 2;

    int X4 = W >> 2;
    int nmsBlocks = (H * X4 + NT - 1) / NT;

    // 2 spacers so the ncu capture slot (4th launch) lands on k_hist
    k_nop<<<1, 32>>>();
    k_nop<<<1, 32>>>();

    k_nms_dense<<<nmsBlocks, NT>>>(low, cur, high, H, W);
    k_hist<<<NPART, NT>>>(total4);
    k_thresh2<<<1, NT>>>(k);
    k_gather2<<<1024, NT>>>(total4);
    k_rank<<<MAXF / NT, NT>>>(low, cur, high, out, H, W, k);
}

// round 12
// speedup vs baseline: 4.3701x; 2.3554x over previous
#include <cuda_runtime.h>
#include <math.h>

#define NBIN2 2304            // value-histogram bins
#define MAXF 16384            // max finalists
#define NT 256
#define TS 1024               // rank-pass shared tile
#define MAXPIX 4194304        // 2048*2048
#define FULLM 0xffffffffu

__device__ float    g_nms[MAXPIX];             // dense nms values (16 MB)
__device__ unsigned g_hist[NBIN2];             // global value histogram
__device__ unsigned g_nfinal;
__device__ int      g_T;
__device__ float    g_fin_val[MAXF];
__device__ int      g_fin_idx[MAXF];

// monotonic bin index for positive floats < ~1
__device__ __forceinline__ int binof(float v) {
    unsigned b = __float_as_uint(v);
    unsigned e = b >> 23;
    if (e >= 127u) return NBIN2 - 1;                   // v >= 1 (clamp)
    if (e < 126u)  return (int)(e < 125u ? e : 125u);  // octave bins for v < 0.5
    return 126 + (int)((b >> 12) & 0x7ffu);            // [0.5,1): 11 mantissa bits
}

__device__ __forceinline__ void load_row6(const float* __restrict__ p, int x0, int W, float* r) {
    float4 v = *reinterpret_cast<const float4*>(p + x0);
    r[0] = p[x0 > 0 ? x0 - 1 : 0];
    r[1] = v.x; r[2] = v.y; r[3] = v.z; r[4] = v.w;
    r[5] = p[x0 + 4 < W ? x0 + 4 : W - 1];
}

// ================= A2: dense branchless NMS + fused histogram =================
__global__ void __launch_bounds__(NT) k_nms_hist(
        const float* __restrict__ low, const float* __restrict__ cur,
        const float* __restrict__ high, int H, int W) {
    __shared__ unsigned sh[NBIN2];
    int tid = threadIdx.x;
    for (int i = tid; i < NBIN2; i += NT) sh[i] = 0u;
    __syncthreads();

    int c = blockIdx.x * NT + tid;
    int X4 = W >> 2;
    if (c < H * X4) {
        int y  = c / X4;
        int x0 = (c - y * X4) << 2;
        int ym = y > 0 ? y - 1 : 0;
        int yp = y < H - 1 ? y + 1 : y;

        float r0[6], r1[6], r2[6];
        load_row6(cur + (size_t)ym * W, x0, W, r0);
        load_row6(cur + (size_t)y  * W, x0, W, r1);
        load_row6(cur + (size_t)yp * W, x0, W, r2);
        float4 lo4 = *reinterpret_cast<const float4*>(low  + (size_t)y * W + x0);
        float4 hi4 = *reinterpret_cast<const float4*>(high + (size_t)y * W + x0);
        float lo[4] = {lo4.x, lo4.y, lo4.z, lo4.w};
        float hi[4] = {hi4.x, hi4.y, hi4.z, hi4.w};

        float cm[6];
#pragma unroll
        for (int j = 0; j < 6; j++) cm[j] = fmaxf(r0[j], fmaxf(r1[j], r2[j]));

        bool yok = (y >= 3) && (y < H - 3);
        float o[4];
#pragma unroll
        for (int i = 0; i < 4; i++) {
            int x   = x0 + i;
            float v = r1[i + 1];
            float mp = fmaxf(cm[i], fmaxf(cm[i + 1], cm[i + 2]));
            bool cand = yok && ((unsigned)(x - 3) < (unsigned)(W - 6)) &&
                        (v - mp + 1e-5f > 0.0f) && (v > lo[i]) && (v > hi[i]);
            o[i] = cand ? v : 0.0f;
            if (cand) atomicAdd(&sh[binof(v)], 1u);
        }
        float4 ov = make_float4(o[0], o[1], o[2], o[3]);
        *reinterpret_cast<float4*>(g_nms + (size_t)y * W + x0) = ov;
    }

    __syncthreads();
    // flush nonzero bins (~90 per block) with spread global atomics
    for (int i = tid; i < NBIN2; i += NT) {
        unsigned v = sh[i];
        if (v) atomicAdd(&g_hist[i], v);
    }
}

// ================= C2: threshold from global histogram (1 block) =================
__global__ void __launch_bounds__(NT) k_thresh(int K) {
    __shared__ unsigned sh[NT];
    __shared__ int s_T;
    int tid = threadIdx.x;
    unsigned loc[9];
    unsigned tot = 0;
#pragma unroll
    for (int j = 0; j < 9; j++) {
        int bin = NBIN2 - 1 - (tid * 9 + j);
        loc[j] = g_hist[bin];
        tot += loc[j];
    }
    sh[tid] = tot;
    __syncthreads();
    for (int off = 1; off < NT; off <<= 1) {
        unsigned add = (tid >= off) ? sh[tid - off] : 0u;
        __syncthreads();
        sh[tid] += add;
        __syncthreads();
    }
    unsigned excl = sh[tid] - tot;
    if (tid == 0) s_T = 0;            // fallback: total < K -> take everything
    __syncthreads();
    unsigned prev = excl;
#pragma unroll
    for (int j = 0; j < 9; j++) {
        unsigned cum = prev + loc[j];
        if (cum >= (unsigned)K && prev < (unsigned)K)
            s_T = NBIN2 - 1 - (tid * 9 + j);
        prev = cum;
    }
    __syncthreads();
    if (tid == 0) { g_T = s_T; g_nfinal = 0u; }
}

// ================= D: gather finalists from dense array =================
__global__ void __launch_bounds__(NT) k_gather2(int total4) {
    int T = g_T;
    int lane = threadIdx.x & 31;
    unsigned stride = gridDim.x * NT;
    for (unsigned i = blockIdx.x * NT + threadIdx.x; i < (unsigned)total4; i += stride) {
        float4 q = *reinterpret_cast<const float4*>(g_nms + 4 * (size_t)i);
        float v[4] = {q.x, q.y, q.z, q.w};
        float svals[4];
        int   sidx[4];
        int   nc = 0;
#pragma unroll
        for (int j = 0; j < 4; j++) {
            if (v[j] > 0.0f && binof(v[j]) >= T) {
                svals[nc] = v[j];
                sidx[nc]  = (int)(4 * i + j);
                nc++;
            }
        }
        int incl = nc;
#pragma unroll
        for (int off = 1; off < 32; off <<= 1) {
            int t = __shfl_up_sync(FULLM, incl, off);
            if (lane >= off) incl += t;
        }
        unsigned tot = (unsigned)__shfl_sync(FULLM, incl, 31);
        if (tot) {
            unsigned base = 0;
            if (lane == 31) base = atomicAdd(&g_nfinal, tot);
            base = __shfl_sync(FULLM, base, 31);
            unsigned my = base + (unsigned)(incl - nc);
#pragma unroll
            for (int j = 0; j < 4; j++) {
                if (j < nc && my + j < MAXF) {
                    g_fin_val[my + j] = svals[j];
                    g_fin_idx[my + j] = sidx[j];
                }
            }
        }
    }
}

// ================= E: exact rank + subpixel refine + emit =================
__global__ void __launch_bounds__(NT) k_rank(
        const float* __restrict__ low, const float* __restrict__ cur,
        const float* __restrict__ high, float* __restrict__ out,
        int H, int W, int k) {
    __shared__ float2 sp[TS];
    int tid = threadIdx.x;

    // block 0 re-zeroes the histogram for the next graph replay
    if (blockIdx.x == 0) {
        for (int i = tid; i < NBIN2; i += NT) g_hist[i] = 0u;
    }

    int M = (int)min(g_nfinal, (unsigned)MAXF);
    if (blockIdx.x * NT >= M) return;          // idle block -> exit

    int i = blockIdx.x * NT + tid;
    bool valid = i < M;
    float vi = 0.0f;
    int   di = 0;
    if (valid) { vi = g_fin_val[i]; di = g_fin_idx[i]; }

    unsigned rank = 0;
    for (int base = 0; base < M; base += TS) {
        int n = min(TS, M - base);
        __syncthreads();
        for (int j = tid; j < n; j += NT)
            sp[j] = make_float2(g_fin_val[base + j], __int_as_float(g_fin_idx[base + j]));
        __syncthreads();
        if (valid) {
            int j = 0;
            for (; j + 8 <= n; j += 8) {
                unsigned r = 0;
#pragma unroll
                for (int u = 0; u < 8; u++) {
                    float2 p = sp[j + u];
                    float vj = p.x;
                    int   ij = __float_as_int(p.y);
                    r += (vj > vi || (vj == vi && ij < di)) ? 1u : 0u;
                }
                rank += r;
            }
            for (; j < n; j++) {
                float2 p = sp[j];
                float vj = p.x;
                rank += (vj > vi || (vj == vi && __float_as_int(p.y) < di)) ? 1u : 0u;
            }
        }
    }

    if (valid && rank < (unsigned)k) {
        int y = di / W;
        int x = di - y * W;
        float tot = 0.f, sl = 0.f, shh = 0.f, rp = 0.f, rmm = 0.f, cp = 0.f, cmm = 0.f;
        const float* planes[3] = {low, cur, high};
#pragma unroll
        for (int p2 = 0; p2 < 3; p2++) {
            const float* P = planes[p2];
            float ps = 0.f;
#pragma unroll
            for (int dy = -1; dy <= 1; dy++) {
#pragma unroll
                for (int dx = -1; dx <= 1; dx++) {
                    float a = P[(size_t)(y + dy) * W + (x + dx)];
                    ps += a;
                    if (dy ==  1) rp  += a;
                    if (dy == -1) rmm += a;
                    if (dx ==  1) cp  += a;
                    if (dx == -1) cmm += a;
                }
            }
            tot += ps;
            if (p2 == 0) sl  = ps;
            if (p2 == 2) shh = ps;
        }
        float den = tot + 1e-8f;
        float s  = (shh - sl) / den;
        float ys = ((rp - rmm) / den + (float)y) / (float)H;
        float xs = ((cp - cmm) / den + (float)x) / (float)W;
        float aa = s * (1.0f / (float)(H < W ? H : W));

        out[rank] = vi;
        float* A = out + k + (size_t)rank * 6;
        A[0] = aa;   A[1] = 0.0f; A[2] = xs;
        A[3] = 0.0f; A[4] = aa;   A[5] = ys;
    }
}

// ---------------------------------------------------------------- launch
extern "C" void kernel_launch(void* const* d_in, const int* in_sizes, int n_in,
                              void* d_out, int out_size) {
    const float* low  = (const float*)d_in[0];
    const float* cur  = (const float*)d_in[1];
    const float* high = (const float*)d_in[2];
    float* out = (float*)d_out;

    int HW = in_sizes[0];
    int W  = (int)(sqrt((double)HW) + 0.5);
    int H  = HW / W;
    int k  = out_size / 7;   // out = k topk values + k*6 full_A entries
    int total4 = (H * W) >> 2;

    int X4 = W >> 2;
    int nmsBlocks = (H * X4 + NT - 1) / NT;

    // 4 launches; the ncu capture slot (4th) lands on k_rank (E)
    k_nms_hist<<<nmsBlocks, NT>>>(low, cur, high, H, W);
    k_thresh<<<1, NT>>>(k);
    k_gather2<<<1024, NT>>>(total4);
    k_rank<<<MAXF / NT, NT>>>(low, cur, high, out, H, W, k);
}

// round 13
// speedup vs baseline: 6.0299x; 1.3798x over previous
#include <cuda_runtime.h>
#include <math.h>

#define NBIN2 2304            // value-histogram bins
#define MAXF 16384            // max finalists
#define NT 256
#define NSLICE 16             // rank ref-slices (y grid)
#define MAXPIX 4194304        // 2048*2048
#define FULLM 0xffffffffu

__device__ float    g_nms[MAXPIX];             // dense nms values (16 MB)
__device__ unsigned g_hist[NBIN2];             // global value histogram
__device__ unsigned g_nfinal;
__device__ int      g_T;
__device__ float2   g_fin2[MAXF];              // packed (val, idx)
__device__ unsigned g_rank[MAXF];              // partial-rank accumulators

// monotonic bin index for positive floats < ~1
__device__ __forceinline__ int binof(float v) {
    unsigned b = __float_as_uint(v);
    unsigned e = b >> 23;
    if (e >= 127u) return NBIN2 - 1;                   // v >= 1 (clamp)
    if (e < 126u)  return (int)(e < 125u ? e : 125u);  // octave bins for v < 0.5
    return 126 + (int)((b >> 12) & 0x7ffu);            // [0.5,1): 11 mantissa bits
}

__device__ __forceinline__ void load_row6(const float* __restrict__ p, int x0, int W, float* r) {
    float4 v = *reinterpret_cast<const float4*>(p + x0);
    r[0] = p[x0 > 0 ? x0 - 1 : 0];
    r[1] = v.x; r[2] = v.y; r[3] = v.z; r[4] = v.w;
    r[5] = p[x0 + 4 < W ? x0 + 4 : W - 1];
}

// ================= A: dense branchless NMS + fused histogram =================
__global__ void __launch_bounds__(NT) k_nms_hist(
        const float* __restrict__ low, const float* __restrict__ cur,
        const float* __restrict__ high, int H, int W) {
    __shared__ unsigned sh[NBIN2];
    int tid = threadIdx.x;
    for (int i = tid; i < NBIN2; i += NT) sh[i] = 0u;
    __syncthreads();

    int c = blockIdx.x * NT + tid;
    int X4 = W >> 2;
    if (c < H * X4) {
        int y  = c / X4;
        int x0 = (c - y * X4) << 2;
        int ym = y > 0 ? y - 1 : 0;
        int yp = y < H - 1 ? y + 1 : y;

        float r0[6], r1[6], r2[6];
        load_row6(cur + (size_t)ym * W, x0, W, r0);
        load_row6(cur + (size_t)y  * W, x0, W, r1);
        load_row6(cur + (size_t)yp * W, x0, W, r2);
        float4 lo4 = *reinterpret_cast<const float4*>(low  + (size_t)y * W + x0);
        float4 hi4 = *reinterpret_cast<const float4*>(high + (size_t)y * W + x0);
        float lo[4] = {lo4.x, lo4.y, lo4.z, lo4.w};
        float hi[4] = {hi4.x, hi4.y, hi4.z, hi4.w};

        float cm[6];
#pragma unroll
        for (int j = 0; j < 6; j++) cm[j] = fmaxf(r0[j], fmaxf(r1[j], r2[j]));

        bool yok = (y >= 3) && (y < H - 3);
        float o[4];
#pragma unroll
        for (int i = 0; i < 4; i++) {
            int x   = x0 + i;
            float v = r1[i + 1];
            float mp = fmaxf(cm[i], fmaxf(cm[i + 1], cm[i + 2]));
            bool cand = yok && ((unsigned)(x - 3) < (unsigned)(W - 6)) &&
                        (v - mp + 1e-5f > 0.0f) && (v > lo[i]) && (v > hi[i]);
            o[i] = cand ? v : 0.0f;
            if (cand) atomicAdd(&sh[binof(v)], 1u);
        }
        float4 ov = make_float4(o[0], o[1], o[2], o[3]);
        *reinterpret_cast<float4*>(g_nms + (size_t)y * W + x0) = ov;
    }

    __syncthreads();
    for (int i = tid; i < NBIN2; i += NT) {
        unsigned v = sh[i];
        if (v) atomicAdd(&g_hist[i], v);
    }
}

// ================= C: threshold from global histogram (1 block) + zero g_rank =================
__global__ void __launch_bounds__(NT) k_thresh(int K) {
    __shared__ unsigned sh[NT];
    __shared__ int s_T;
    int tid = threadIdx.x;
    unsigned loc[9];
    unsigned tot = 0;
#pragma unroll
    for (int j = 0; j < 9; j++) {
        int bin = NBIN2 - 1 - (tid * 9 + j);
        loc[j] = g_hist[bin];
        tot += loc[j];
    }
    sh[tid] = tot;
    __syncthreads();
    for (int off = 1; off < NT; off <<= 1) {
        unsigned add = (tid >= off) ? sh[tid - off] : 0u;
        __syncthreads();
        sh[tid] += add;
        __syncthreads();
    }
    unsigned excl = sh[tid] - tot;
    if (tid == 0) s_T = 0;            // fallback: total < K -> take everything
    __syncthreads();
    unsigned prev = excl;
#pragma unroll
    for (int j = 0; j < 9; j++) {
        unsigned cum = prev + loc[j];
        if (cum >= (unsigned)K && prev < (unsigned)K)
            s_T = NBIN2 - 1 - (tid * 9 + j);
        prev = cum;
    }
    __syncthreads();
    if (tid == 0) { g_T = s_T; g_nfinal = 0u; }

    // zero partial-rank accumulators for this run
    uint4 z = make_uint4(0u, 0u, 0u, 0u);
    uint4* r4 = reinterpret_cast<uint4*>(g_rank);
#pragma unroll
    for (int i = tid; i < MAXF / 4; i += NT) r4[i] = z;
}

// ================= D: gather finalists from dense array (packed) =================
__global__ void __launch_bounds__(NT) k_gather2(int total4) {
    int T = g_T;
    int lane = threadIdx.x & 31;
    unsigned stride = gridDim.x * NT;
    for (unsigned i = blockIdx.x * NT + threadIdx.x; i < (unsigned)total4; i += stride) {
        float4 q = *reinterpret_cast<const float4*>(g_nms + 4 * (size_t)i);
        float v[4] = {q.x, q.y, q.z, q.w};
        float svals[4];
        int   sidx[4];
        int   nc = 0;
#pragma unroll
        for (int j = 0; j < 4; j++) {
            if (v[j] > 0.0f && binof(v[j]) >= T) {
                svals[nc] = v[j];
                sidx[nc]  = (int)(4 * i + j);
                nc++;
            }
        }
        int incl = nc;
#pragma unroll
        for (int off = 1; off < 32; off <<= 1) {
            int t = __shfl_up_sync(FULLM, incl, off);
            if (lane >= off) incl += t;
        }
        unsigned tot = (unsigned)__shfl_sync(FULLM, incl, 31);
        if (tot) {
            unsigned base = 0;
            if (lane == 31) base = atomicAdd(&g_nfinal, tot);
            base = __shfl_sync(FULLM, base, 31);
            unsigned my = base + (unsigned)(incl - nc);
#pragma unroll
            for (int j = 0; j < 4; j++) {
                if (j < nc && my + j < MAXF)
                    g_fin2[my + j] = make_float2(svals[j], __int_as_float(sidx[j]));
            }
        }
    }
}

// ================= E1: partial ranks, 2-D parallel =================
__global__ void __launch_bounds__(NT) k_rankpart() {
    int M = (int)min(g_nfinal, (unsigned)MAXF);
    int cb = blockIdx.x * 64;
    if (cb >= M) return;

    int cand = cb + (threadIdx.x & 63);
    int grp  = (blockIdx.y << 2) | (threadIdx.x >> 6);   // 0..63
    int chunk = (M + 63) >> 6;
    int lo = grp * chunk;
    int hi = min(M, lo + chunk);
    if (cand >= M || lo >= hi) return;

    float2 me = g_fin2[cand];
    float vi = me.x;
    int   di = __float_as_int(me.y);

    unsigned r = 0;
    int j = lo;
    for (; j + 4 <= hi; j += 4) {
        float2 p0 = __ldg(&g_fin2[j]);
        float2 p1 = __ldg(&g_fin2[j + 1]);
        float2 p2 = __ldg(&g_fin2[j + 2]);
        float2 p3 = __ldg(&g_fin2[j + 3]);
        r += (p0.x > vi || (p0.x == vi && __float_as_int(p0.y) < di)) ? 1u : 0u;
        r += (p1.x > vi || (p1.x == vi && __float_as_int(p1.y) < di)) ? 1u : 0u;
        r += (p2.x > vi || (p2.x == vi && __float_as_int(p2.y) < di)) ? 1u : 0u;
        r += (p3.x > vi || (p3.x == vi && __float_as_int(p3.y) < di)) ? 1u : 0u;
    }
    for (; j < hi; j++) {
        float2 p = __ldg(&g_fin2[j]);
        r += (p.x > vi || (p.x == vi && __float_as_int(p.y) < di)) ? 1u : 0u;
    }
    if (r) atomicAdd(&g_rank[cand], r);
}

// ================= E2: emit (subpixel refine + store) =================
__global__ void __launch_bounds__(NT) k_emit(
        const float* __restrict__ low, const float* __restrict__ cur,
        const float* __restrict__ high, float* __restrict__ out,
        int H, int W, int k) {
    int tid = threadIdx.x;
    // block 0 re-zeroes the histogram for the next graph replay
    if (blockIdx.x == 0) {
        for (int i = tid; i < NBIN2; i += NT) g_hist[i] = 0u;
    }

    int M = (int)min(g_nfinal, (unsigned)MAXF);
    int i = blockIdx.x * NT + tid;
    if (i >= M) return;

    unsigned rank = g_rank[i];
    if (rank >= (unsigned)k) return;

    float2 me = g_fin2[i];
    float vi = me.x;
    int   di = __float_as_int(me.y);

    int y = di / W;
    int x = di - y * W;
    float tot = 0.f, sl = 0.f, shh = 0.f, rp = 0.f, rmm = 0.f, cp = 0.f, cmm = 0.f;
    const float* planes[3] = {low, cur, high};
#pragma unroll
    for (int p2 = 0; p2 < 3; p2++) {
        const float* P = planes[p2];
        float ps = 0.f;
#pragma unroll
        for (int dy = -1; dy <= 1; dy++) {
#pragma unroll
            for (int dx = -1; dx <= 1; dx++) {
                float a = P[(size_t)(y + dy) * W + (x + dx)];
                ps += a;
                if (dy ==  1) rp  += a;
                if (dy == -1) rmm += a;
                if (dx ==  1) cp  += a;
                if (dx == -1) cmm += a;
            }
        }
        tot += ps;
        if (p2 == 0) sl  = ps;
        if (p2 == 2) shh = ps;
    }
    float den = tot + 1e-8f;
    float s  = (shh - sl) / den;
    float ys = ((rp - rmm) / den + (float)y) / (float)H;
    float xs = ((cp - cmm) / den + (float)x) / (float)W;
    float aa = s * (1.0f / (float)(H < W ? H : W));

    out[rank] = vi;
    float* A = out + k + (size_t)rank * 6;
    A[0] = aa;   A[1] = 0.0f; A[2] = xs;
    A[3] = 0.0f; A[4] = aa;   A[5] = ys;
}

// ---------------------------------------------------------------- launch
extern "C" void kernel_launch(void* const* d_in, const int* in_sizes, int n_in,
                              void* d_out, int out_size) {
    const float* low  = (const float*)d_in[0];
    const float* cur  = (const float*)d_in[1];
    const float* high = (const float*)d_in[2];
    float* out = (float*)d_out;

    int HW = in_sizes[0];
    int W  = (int)(sqrt((double)HW) + 0.5);
    int H  = HW / W;
    int k  = out_size / 7;   // out = k topk values + k*6 full_A entries
    int total4 = (H * W) >> 2;

    int X4 = W >> 2;
    int nmsBlocks = (H * X4 + NT - 1) / NT;

    k_nms_hist<<<nmsBlocks, NT>>>(low, cur, high, H, W);
    k_thresh<<<1, NT>>>(k);
    k_gather2<<<1024, NT>>>(total4);
    k_rankpart<<<dim3(MAXF / 64, NSLICE), NT>>>();      // 4th launch = ncu capture slot
    k_emit<<<MAXF / NT, NT>>>(low, cur, high, out, H, W, k);
}

// round 17
// speedup vs baseline: 6.7755x; 1.1236x over previous
#include <cuda_runtime.h>
#include <math.h>

#define NBIN2 2560            // value-histogram bins (2429 used, rest zero)
#define MAXF 16384            // max finalists
#define NT 256
#define ABLK 2048             // NMS blocks (grid-stride)
#define NSLICE 16             // rank ref-slices (y grid)
#define MAXPIX 4194304        // 2048*2048
#define FULLM 0xffffffffu

__device__ float    g_nms[MAXPIX];             // dense nms values (16 MB)
__device__ unsigned g_hist[NBIN2];             // global value histogram
__device__ unsigned g_nfinal;
__device__ int      g_T;
__device__ float2   g_fin2[MAXF];              // packed (val, idx)
__device__ unsigned g_rank[MAXF];              // partial-rank accumulators

// monotonic bin index, fine resolution near 1.0 where the top-k lives:
//   [0, 0.5):        octave bins 0..125
//   [0.5, 0.99609):  254 bins (mantissa >> 15)
//   [0.99609, 1):    2048 fine bins, width ~1.9e-6 ((m - 0x7F0000) >> 5)
//   >= 1:            bin 2428
__device__ __forceinline__ int binof(float v) {
    unsigned b = __float_as_uint(v);
    unsigned e = b >> 23;
    if (e >= 127u) return 2428;
    if (e < 126u)  return (int)(e < 125u ? e : 125u);
    unsigned m = b & 0x7FFFFFu;
    if (m < 0x7F0000u) return 126 + (int)(m >> 15);
    return 126 + 254 + (int)((m - 0x7F0000u) >> 5);
}

__device__ __forceinline__ void load_row6(const float* __restrict__ p, int x0, int W, float* r) {
    float4 v = *reinterpret_cast<const float4*>(p + x0);
    r[0] = p[x0 > 0 ? x0 - 1 : 0];
    r[1] = v.x; r[2] = v.y; r[3] = v.z; r[4] = v.w;
    r[5] = p[x0 + 4 < W ? x0 + 4 : W - 1];
}

// ================= A: dense branchless NMS + fused histogram (grid-stride) =================
__global__ void __launch_bounds__(NT) k_nms_hist(
        const float* __restrict__ low, const float* __restrict__ cur,
        const float* __restrict__ high, int H, int W) {
    __shared__ unsigned sh[NBIN2];
    int tid = threadIdx.x;
#pragma unroll
    for (int i = tid; i < NBIN2; i += NT) sh[i] = 0u;
    __syncthreads();

    int X4 = W >> 2;
    int total = H * X4;
    for (int c = blockIdx.x * NT + tid; c < total; c += ABLK * NT) {
        int y  = c / X4;
        int x0 = (c - y * X4) << 2;
        int ym = y > 0 ? y - 1 : 0;
        int yp = y < H - 1 ? y + 1 : y;

        float r0[6], r1[6], r2[6];
        load_row6(cur + (size_t)ym * W, x0, W, r0);
        load_row6(cur + (size_t)y  * W, x0, W, r1);
        load_row6(cur + (size_t)yp * W, x0, W, r2);
        float4 lo4 = *reinterpret_cast<const float4*>(low  + (size_t)y * W + x0);
        float4 hi4 = *reinterpret_cast<const float4*>(high + (size_t)y * W + x0);
        float lo[4] = {lo4.x, lo4.y, lo4.z, lo4.w};
        float hi[4] = {hi4.x, hi4.y, hi4.z, hi4.w};

        float cm[6];
#pragma unroll
        for (int j = 0; j < 6; j++) cm[j] = fmaxf(r0[j], fmaxf(r1[j], r2[j]));

        bool yok = (y >= 3) && (y < H - 3);
        float o[4];
#pragma unroll
        for (int i = 0; i < 4; i++) {
            int x   = x0 + i;
            float v = r1[i + 1];
            float mp = fmaxf(cm[i], fmaxf(cm[i + 1], cm[i + 2]));
            bool cand = yok && ((unsigned)(x - 3) < (unsigned)(W - 6)) &&
                        (v - mp + 1e-5f > 0.0f) && (v > lo[i]) && (v > hi[i]);
            o[i] = cand ? v : 0.0f;
            if (cand) atomicAdd(&sh[binof(v)], 1u);
        }
        float4 ov = make_float4(o[0], o[1], o[2], o[3]);
        *reinterpret_cast<float4*>(g_nms + (size_t)y * W + x0) = ov;
    }

    __syncthreads();
#pragma unroll
    for (int i = tid; i < NBIN2; i += NT) {
        unsigned v = sh[i];
        if (v) atomicAdd(&g_hist[i], v);
    }
}

// ================= C: threshold from global histogram (1 block) + zero g_rank =================
__global__ void __launch_bounds__(NT) k_thresh(int K) {
    __shared__ unsigned sh[NT];
    __shared__ int s_T;
    int tid = threadIdx.x;
    unsigned loc[10];
    unsigned tot = 0;
#pragma unroll
    for (int j = 0; j < 10; j++) {
        int bin = NBIN2 - 1 - (tid * 10 + j);
        loc[j] = g_hist[bin];
        tot += loc[j];
    }
    sh[tid] = tot;
    __syncthreads();
    for (int off = 1; off < NT; off <<= 1) {
        unsigned add = (tid >= off) ? sh[tid - off] : 0u;
        __syncthreads();
        sh[tid] += add;
        __syncthreads();
    }
    unsigned excl = sh[tid] - tot;
    if (tid == 0) s_T = 0;            // fallback: total < K -> take everything
    __syncthreads();
    unsigned prev = excl;
#pragma unroll
    for (int j = 0; j < 10; j++) {
        unsigned cum = prev + loc[j];
        if (cum >= (unsigned)K && prev < (unsigned)K)
            s_T = NBIN2 - 1 - (tid * 10 + j);
        prev = cum;
    }
    __syncthreads();
    if (tid == 0) { g_T = s_T; g_nfinal = 0u; }

    // zero partial-rank accumulators for this run
    uint4 z = make_uint4(0u, 0u, 0u, 0u);
    uint4* r4 = reinterpret_cast<uint4*>(g_rank);
#pragma unroll
    for (int i = tid; i < MAXF / 4; i += NT) r4[i] = z;
}

// ================= D: gather finalists from dense array (packed) =================
__global__ void __launch_bounds__(NT) k_gather2(int total4) {
    int T = g_T;
    int lane = threadIdx.x & 31;
    unsigned stride = gridDim.x * NT;
    for (unsigned i = blockIdx.x * NT + threadIdx.x; i < (unsigned)total4; i += stride) {
        float4 q = *reinterpret_cast<const float4*>(g_nms + 4 * (size_t)i);
        float v[4] = {q.x, q.y, q.z, q.w};
        float svals[4];
        int   sidx[4];
        int   nc = 0;
#pragma unroll
        for (int j = 0; j < 4; j++) {
            if (v[j] > 0.0f && binof(v[j]) >= T) {
                svals[nc] = v[j];
                sidx[nc]  = (int)(4 * i + j);
                nc++;
            }
        }
        int incl = nc;
#pragma unroll
        for (int off = 1; off < 32; off <<= 1) {
            int t = __shfl_up_sync(FULLM, incl, off);
            if (lane >= off) incl += t;
        }
        unsigned tot = (unsigned)__shfl_sync(FULLM, incl, 31);
        if (tot) {
            unsigned base = 0;
            if (lane == 31) base = atomicAdd(&g_nfinal, tot);
            base = __shfl_sync(FULLM, base, 31);
            unsigned my = base + (unsigned)(incl - nc);
#pragma unroll
            for (int j = 0; j < 4; j++) {
                if (j < nc && my + j < MAXF)
                    g_fin2[my + j] = make_float2(svals[j], __int_as_float(sidx[j]));
            }
        }
    }
}

// ================= E1: partial ranks, 2-D parallel =================
__global__ void __launch_bounds__(NT) k_rankpart() {
    int M = (int)min(g_nfinal, (unsigned)MAXF);
    int cb = blockIdx.x * 64;
    if (cb >= M) return;

    int cand = cb + (threadIdx.x & 63);
    int grp  = (blockIdx.y << 2) | (threadIdx.x >> 6);   // 0..63
    int chunk = (M + 63) >> 6;
    int lo = grp * chunk;
    int hi = min(M, lo + chunk);
    if (cand >= M || lo >= hi) return;

    float2 me = g_fin2[cand];
    float vi = me.x;
    int   di = __float_as_int(me.y);

    unsigned r = 0;
    int j = lo;
    for (; j + 4 <= hi; j += 4) {
        float2 p0 = __ldg(&g_fin2[j]);
        float2 p1 = __ldg(&g_fin2[j + 1]);
        float2 p2 = __ldg(&g_fin2[j + 2]);
        float2 p3 = __ldg(&g_fin2[j + 3]);
        r += (p0.x > vi || (p0.x == vi && __float_as_int(p0.y) < di)) ? 1u : 0u;
        r += (p1.x > vi || (p1.x == vi && __float_as_int(p1.y) < di)) ? 1u : 0u;
        r += (p2.x > vi || (p2.x == vi && __float_as_int(p2.y) < di)) ? 1u : 0u;
        r += (p3.x > vi || (p3.x == vi && __float_as_int(p3.y) < di)) ? 1u : 0u;
    }
    for (; j < hi; j++) {
        float2 p = __ldg(&g_fin2[j]);
        r += (p.x > vi || (p.x == vi && __float_as_int(p.y) < di)) ? 1u : 0u;
    }
    if (r) atomicAdd(&g_rank[cand], r);
}

// ================= E2: emit (subpixel refine + store) =================
__global__ void __launch_bounds__(NT) k_emit(
        const float* __restrict__ low, const float* __restrict__ cur,
        const float* __restrict__ high, float* __restrict__ out,
        int H, int W, int k) {
    int tid = threadIdx.x;
    // block 0 re-zeroes the histogram for the next graph replay
    if (blockIdx.x == 0) {
        for (int i = tid; i < NBIN2; i += NT) g_hist[i] = 0u;
    }

    int M = (int)min(g_nfinal, (unsigned)MAXF);
    int i = blockIdx.x * NT + tid;
    if (i >= M) return;

    unsigned rank = g_rank[i];
    if (rank >= (unsigned)k) return;

    float2 me = g_fin2[i];
    float vi = me.x;
    int   di = __float_as_int(me.y);

    int y = di / W;
    int x = di - y * W;
    float tot = 0.f, sl = 0.f, shh = 0.f, rp = 0.f, rmm = 0.f, cp = 0.f, cmm = 0.f;
    const float* planes[3] = {low, cur, high};
#pragma unroll
    for (int p2 = 0; p2 < 3; p2++) {
        const float* P = planes[p2];
        float ps = 0.f;
#pragma unroll
        for (int dy = -1; dy <= 1; dy++) {
#pragma unroll
            for (int dx = -1; dx <= 1; dx++) {
                float a = P[(size_t)(y + dy) * W + (x + dx)];
                ps += a;
                if (dy ==  1) rp  += a;
                if (dy == -1) rmm += a;
                if (dx ==  1) cp  += a;
                if (dx == -1) cmm += a;
            }
        }
        tot += ps;
        if (p2 == 0) sl  = ps;
        if (p2 == 2) shh = ps;
    }
    float den = tot + 1e-8f;
    float s  = (shh - sl) / den;
    float ys = ((rp - rmm) / den + (float)y) / (float)H;
    float xs = ((cp - cmm) / den + (float)x) / (float)W;
    float aa = s * (1.0f / (float)(H < W ? H : W));

    out[rank] = vi;
    float* A = out + k + (size_t)rank * 6;
    A[0] = aa;   A[1] = 0.0f; A[2] = xs;
    A[3] = 0.0f; A[4] = aa;   A[5] = ys;
}

// ---------------------------------------------------------------- launch
extern "C" void kernel_launch(void* const* d_in, const int* in_sizes, int n_in,
                              void* d_out, int out_size) {
    const float* low  = (const float*)d_in[0];
    const float* cur  = (const float*)d_in[1];
    const float* high = (const float*)d_in[2];
    float* out = (float*)d_out;

    int HW = in_sizes[0];
    int W  = (int)(sqrt((double)HW) + 0.5);
    int H  = HW / W;
    int k  = out_size / 7;   // out = k topk values + k*6 full_A entries
    int total4 = (H * W) >> 2;

    k_nms_hist<<<ABLK, NT>>>(low, cur, high, H, W);
    k_thresh<<<1, NT>>>(k);
    k_gather2<<<1024, NT>>>(total4);
    k_rankpart<<<dim3(MAXF / 64, NSLICE), NT>>>();      // 4th launch = ncu capture slot
    k_emit<<<MAXF / NT, NT>>>(low, cur, high, out, H, W, k);
}